// round 15
// baseline (speedup 1.0000x reference)
#include <cuda_runtime.h>
#include <cuda_fp16.h>
#include <math.h>
#include <stdint.h>

#define EMBED   1024
#define NHEAD   16
#define HD      64
#define BATCH   2
#define SEQ     2048
#define TOKENS  (BATCH * SEQ)      // 4096
#define QKV_N   (3 * EMBED)        // 3072

// ---------------------------------------------------------------------------
// Scratch
// ---------------------------------------------------------------------------
__device__ __half g_x  [(size_t)TOKENS * EMBED];
__device__ __half g_wqkv[(size_t)QKV_N * EMBED];
__device__ __half g_wp [(size_t)EMBED * EMBED];
__device__ __half g_at [(size_t)TOKENS * EMBED];
#define HEADELEMS ((size_t)BATCH * NHEAD * SEQ * HD)
__device__ __half g_q[HEADELEMS], g_k[HEADELEMS], g_v[HEADELEMS];

// ---------------------------------------------------------------------------
// helpers
// ---------------------------------------------------------------------------
__device__ __forceinline__ uint32_t smem_u32(const void* p) {
    uint32_t a;
    asm("{ .reg .u64 t; cvta.to.shared.u64 t, %1; cvt.u32.u64 %0, t; }"
        : "=r"(a) : "l"(p));
    return a;
}
__device__ __forceinline__ void cp_async16(uint32_t s, const void* g) {
    asm volatile("cp.async.cg.shared.global [%0], [%1], 16;" :: "r"(s), "l"(g));
}
#define CP_COMMIT() asm volatile("cp.async.commit_group;" ::: "memory")
#define CP_WAIT1()  asm volatile("cp.async.wait_group 1;" ::: "memory")
#define CP_WAIT0()  asm volatile("cp.async.wait_group 0;" ::: "memory")

__device__ __forceinline__ void ldm_x4(uint32_t* r, uint32_t addr) {
    asm volatile("ldmatrix.sync.aligned.m8n8.x4.shared.b16 {%0,%1,%2,%3}, [%4];"
                 : "=r"(r[0]), "=r"(r[1]), "=r"(r[2]), "=r"(r[3]) : "r"(addr));
}
__device__ __forceinline__ void ldm_x4t(uint32_t* r, uint32_t addr) {
    asm volatile("ldmatrix.sync.aligned.m8n8.x4.trans.shared.b16 {%0,%1,%2,%3}, [%4];"
                 : "=r"(r[0]), "=r"(r[1]), "=r"(r[2]), "=r"(r[3]) : "r"(addr));
}
__device__ __forceinline__ void mma_f16(float* c, const uint32_t* a,
                                        uint32_t b0, uint32_t b1) {
    asm volatile("mma.sync.aligned.m16n8k16.row.col.f32.f16.f16.f32 "
                 "{%0,%1,%2,%3}, {%4,%5,%6,%7}, {%8,%9}, {%0,%1,%2,%3};"
                 : "+f"(c[0]), "+f"(c[1]), "+f"(c[2]), "+f"(c[3])
                 : "r"(a[0]), "r"(a[1]), "r"(a[2]), "r"(a[3]), "r"(b0), "r"(b1));
}
__device__ __forceinline__ uint32_t pack_h2(float x, float y) {
    __half2 v = __floats2half2_rn(x, y);
    return *(uint32_t*)&v;
}
__device__ __forceinline__ float ex2(float x) {
    float r; asm("ex2.approx.f32 %0, %1;" : "=f"(r) : "f"(x)); return r;
}

// ---------------------------------------------------------------------------
// fp32 -> fp16 for all three inputs in one launch
// ---------------------------------------------------------------------------
#define NX4 (TOKENS * EMBED / 4)
#define NQ4 (QKV_N * EMBED / 4)
#define NP4 (EMBED * EMBED / 4)

__global__ void tohalf_all(const float4* __restrict__ x,
                           const float4* __restrict__ wq,
                           const float4* __restrict__ wp)
{
    int i = blockIdx.x * blockDim.x + threadIdx.x;
    const float4* src;
    uint32_t* dst;
    int j;
    if (i < NX4)                 { src = x;  dst = (uint32_t*)g_x;    j = i; }
    else if (i < NX4 + NQ4)      { src = wq; dst = (uint32_t*)g_wqkv; j = i - NX4; }
    else if (i < NX4 + NQ4 + NP4){ src = wp; dst = (uint32_t*)g_wp;   j = i - NX4 - NQ4; }
    else return;
    float4 v = src[j];
    dst[2 * j + 0] = pack_h2(v.x, v.y);
    dst[2 * j + 1] = pack_h2(v.z, v.w);
}

// ---------------------------------------------------------------------------
// HMMA fp16 GEMM (unchanged from R14): CTA 128x128, BK=64, 8 warps (64x32),
// 3-stage cp.async, 1 sync/chunk, 144B rows.
// MODE 0: fp32 C + bias.  MODE 1: QKV epilogue -> per-head q/k/v.
// ---------------------------------------------------------------------------
#define GROWB  144
#define GTILE  (128 * GROWB)   // 18432
#define GSTG   (2 * GTILE)     // 36864
#define G_SMEM (3 * GSTG)      // 110592
#define CROW   272

template <int MODE>
__global__ __launch_bounds__(256)
void gemm_f16(const __half* __restrict__ A, const __half* __restrict__ B,
              const float* __restrict__ bias, float* __restrict__ C,
              int M, int N, int K)
{
    extern __shared__ char smem[];
    const uint32_t sb = smem_u32(smem);
    const int tid  = threadIdx.x;
    const int wid  = tid >> 5;
    const int lane = tid & 31;
    const int warp_m = wid & 1;
    const int warp_n = wid >> 1;
    const int m0 = blockIdx.y * 128;
    const int n0 = blockIdx.x * 128;

    const __half* gA = A + (size_t)m0 * K;
    const __half* gB = B + (size_t)n0 * K;

    float acc[4][4][4];
#pragma unroll
    for (int i = 0; i < 4; i++)
#pragma unroll
        for (int j = 0; j < 4; j++)
#pragma unroll
            for (int f = 0; f < 4; f++) acc[i][j][f] = 0.0f;

    const int nk = K >> 6;

    {
        uint32_t sT = sb;
#pragma unroll
        for (int i = 0; i < 8; i++) {
            int chunk = tid + i * 256;
            int tile = chunk >> 10;
            int r = (chunk >> 3) & 127;
            int col = (chunk & 7) * 16;
            const __half* src = tile ? gB : gA;
            cp_async16(sT + tile * GTILE + r * GROWB + col,
                       (const char*)(src + (size_t)r * K) + col);
        }
    }
    CP_COMMIT();

    const uint32_t a_off = (uint32_t)(warp_m * 64 + (lane & 15)) * GROWB + (lane >> 4) * 16;
    const uint32_t b_off = (uint32_t)(warp_n * 32 + (lane & 15)) * GROWB + (lane >> 4) * 16;

    int buf = 0, nxt = 1;
    for (int c = 0; c < nk; c++) {
        if (c + 1 < nk) {
            const int kb = (c + 1) * 128;
            uint32_t sT = sb + nxt * GSTG;
#pragma unroll
            for (int i = 0; i < 8; i++) {
                int chunk = tid + i * 256;
                int tile = chunk >> 10;
                int r = (chunk >> 3) & 127;
                int col = (chunk & 7) * 16;
                const __half* src = tile ? gB : gA;
                cp_async16(sT + tile * GTILE + r * GROWB + col,
                           (const char*)(src + (size_t)r * K) + kb + col);
            }
            CP_COMMIT();
            CP_WAIT1();
        } else {
            CP_WAIT0();
        }
        __syncthreads();

        const uint32_t st = sb + buf * GSTG;
#pragma unroll
        for (int ks = 0; ks < 4; ks++) {
            const uint32_t ko = ks * 32;
            uint32_t af[4][4], bf[2][4];
#pragma unroll
            for (int mt = 0; mt < 4; mt++)
                ldm_x4(af[mt], st + a_off + mt * 16 * GROWB + ko);
#pragma unroll
            for (int bt = 0; bt < 2; bt++)
                ldm_x4(bf[bt], st + GTILE + b_off + bt * 16 * GROWB + ko);
#pragma unroll
            for (int mt = 0; mt < 4; mt++)
#pragma unroll
                for (int nt = 0; nt < 4; nt++) {
                    const int bt = nt >> 1, p = nt & 1;
                    mma_f16(acc[mt][nt], af[mt], bf[bt][p], bf[bt][p + 2]);
                }
        }
        buf = nxt; nxt = nxt + 1 == 3 ? 0 : nxt + 1;
    }

    const int gr = lane >> 2;
    const int gc = (lane & 3) << 1;

    if (MODE == 0) {
#pragma unroll
        for (int mt = 0; mt < 4; mt++) {
            const int row = m0 + warp_m * 64 + mt * 16 + gr;
#pragma unroll
            for (int nt = 0; nt < 4; nt++) {
                const int col = n0 + warp_n * 32 + nt * 8 + gc;
                const float b0 = bias[col], b1 = bias[col + 1];
                *(float2*)(C + (size_t)row * N + col) =
                    make_float2(acc[mt][nt][0] + b0, acc[mt][nt][1] + b1);
                *(float2*)(C + (size_t)(row + 8) * N + col) =
                    make_float2(acc[mt][nt][2] + b0, acc[mt][nt][3] + b1);
            }
        }
    } else {
        __syncthreads();
        const float sc = (n0 >> 10) == 0 ? 0.125f * 1.44269504f : 1.0f;
#pragma unroll
        for (int mt = 0; mt < 4; mt++) {
            const int r0l = warp_m * 64 + mt * 16 + gr;
#pragma unroll
            for (int nt = 0; nt < 4; nt++) {
                const int cl = warp_n * 32 + nt * 8 + gc;
                const float b0 = bias[n0 + cl], b1 = bias[n0 + cl + 1];
                *(uint32_t*)(smem + r0l * CROW + cl * 2) =
                    pack_h2((acc[mt][nt][0] + b0) * sc, (acc[mt][nt][1] + b1) * sc);
                *(uint32_t*)(smem + (r0l + 8) * CROW + cl * 2) =
                    pack_h2((acc[mt][nt][2] + b0) * sc, (acc[mt][nt][3] + b1) * sc);
            }
        }
        __syncthreads();

        const int t = n0 >> 10;
        __half* dp = t == 0 ? g_q : (t == 1 ? g_k : g_v);
        const int bb  = m0 >> 11;
        const int sq0 = m0 & (SEQ - 1);
        const int j = tid & 7;
#pragma unroll
        for (int ch = 0; ch < 2; ch++) {
            const int hh = ((n0 + ch * 64) >> 6) & (NHEAD - 1);
            const size_t base = (((size_t)(bb * NHEAD + hh)) * SEQ + sq0) * HD;
#pragma unroll
            for (int it = 0; it < 4; it++) {
                const int row = (tid >> 3) + it * 32;
                uint4 v = *(const uint4*)(smem + row * CROW + ch * 128 + j * 16);
                *(uint4*)((char*)(dp + base + (size_t)row * HD) + j * 16) = v;
            }
        }
    }
}

// ---------------------------------------------------------------------------
// HMMA flash attention: BQ=64 (fine-grained grid: 1024 CTAs -> 1.012 wave
// quantization), 4 warps x 16 q-rows, direct-GMEM Q fragments, 2-stage KV
// ring (BKV=128) with load-after-sync WAR safety, 3 CTAs/SM; base-2 softmax;
// lane-local l-sum reduced at epilogue.
// ---------------------------------------------------------------------------
#define BQ     64
#define BKV    128
#define KROWB  144
#define F_T    (BKV * KROWB)       // 18432
#define F_STG  (2 * F_T)           // 36864
#define F_SMEM (2 * F_STG)         // 73728
#define NKV    (SEQ / BKV)         // 16

__global__ __launch_bounds__(128, 3)
void flash_f16(const __half* __restrict__ qq, const __half* __restrict__ kk,
               const __half* __restrict__ vv, __half* __restrict__ oo)
{
    extern __shared__ char smem[];
    const uint32_t sb = smem_u32(smem);
    const int tid = threadIdx.x;
    const int wid = tid >> 5;          // 0..3
    const int lane = tid & 31;

    const int q0 = blockIdx.x * BQ;
    const int h  = blockIdx.y;
    const int b  = blockIdx.z;
    const size_t hoff = ((size_t)(b * NHEAD + h)) * SEQ * HD;

    // KV tile 0 -> stage 0 (2048 x 16B chunks, 16 per thread)
#pragma unroll
    for (int i = 0; i < 16; i++) {
        int chunk = tid + i * 128;
        int tensor = chunk >> 10;
        int row = (chunk >> 3) & 127;
        int col = (chunk & 7) * 16;
        const __half* src = tensor ? vv : kk;
        cp_async16(sb + tensor * F_T + row * KROWB + col,
                   (const char*)(src + hoff + (size_t)row * HD) + col);
    }
    CP_COMMIT();

    // Q fragments directly from GMEM
    uint32_t qf[4][4];
    {
        const int r  = wid * 16 + (lane >> 2);
        const int c  = (lane & 3) * 2;
        const __half* q_r0 = qq + hoff + (size_t)(q0 + r) * HD;
        const __half* q_r1 = q_r0 + 8 * HD;
#pragma unroll
        for (int kt = 0; kt < 4; kt++) {
            qf[kt][0] = *(const uint32_t*)(q_r0 + kt * 16 + c);
            qf[kt][1] = *(const uint32_t*)(q_r1 + kt * 16 + c);
            qf[kt][2] = *(const uint32_t*)(q_r0 + kt * 16 + c + 8);
            qf[kt][3] = *(const uint32_t*)(q_r1 + kt * 16 + c + 8);
        }
    }

    float o[8][4];
#pragma unroll
    for (int nt = 0; nt < 8; nt++)
#pragma unroll
        for (int f = 0; f < 4; f++) o[nt][f] = 0.0f;
    float m0r = -INFINITY, m1r = -INFINITY;
    float l0r = 0.0f, l1r = 0.0f;

    for (int t = 0; t < NKV; t++) {
        CP_WAIT0();        // load(t) complete (only group in flight)
        __syncthreads();   // all warps done reading the stage being refilled
        if (t + 1 < NKV) {
            const int key0 = (t + 1) * BKV;
            const uint32_t dstb = sb + ((t + 1) & 1) * F_STG;
#pragma unroll
            for (int i = 0; i < 16; i++) {
                int chunk = tid + i * 128;
                int tensor = chunk >> 10;
                int row = (chunk >> 3) & 127;
                int col = (chunk & 7) * 16;
                const __half* src = tensor ? vv : kk;
                cp_async16(dstb + tensor * F_T + row * KROWB + col,
                           (const char*)(src + hoff + (size_t)(key0 + row) * HD) + col);
            }
            CP_COMMIT();
        }

        const uint32_t kvb = sb + (t & 1) * F_STG;

#pragma unroll
        for (int sub = 0; sub < 2; sub++) {
            const uint32_t koff = (uint32_t)(sub * 64) * KROWB;

            float s[8][4];
#pragma unroll
            for (int nt = 0; nt < 8; nt++)
#pragma unroll
                for (int f = 0; f < 4; f++) s[nt][f] = 0.0f;

#pragma unroll
            for (int ntp = 0; ntp < 4; ntp++) {
                const uint32_t ka = kvb + koff
                    + (uint32_t)(ntp * 16 + (lane & 15)) * KROWB + 16 * (lane >> 4);
#pragma unroll
                for (int kt = 0; kt < 4; kt++) {
                    uint32_t kf[4];
                    ldm_x4(kf, ka + kt * 32);
                    mma_f16(s[2 * ntp],     qf[kt], kf[0], kf[2]);
                    mma_f16(s[2 * ntp + 1], qf[kt], kf[1], kf[3]);
                }
            }

            float mx0 = -INFINITY, mx1 = -INFINITY;
#pragma unroll
            for (int nt = 0; nt < 8; nt++) {
                mx0 = fmaxf(mx0, fmaxf(s[nt][0], s[nt][1]));
                mx1 = fmaxf(mx1, fmaxf(s[nt][2], s[nt][3]));
            }
            mx0 = fmaxf(mx0, __shfl_xor_sync(0xffffffffu, mx0, 1));
            mx0 = fmaxf(mx0, __shfl_xor_sync(0xffffffffu, mx0, 2));
            mx1 = fmaxf(mx1, __shfl_xor_sync(0xffffffffu, mx1, 1));
            mx1 = fmaxf(mx1, __shfl_xor_sync(0xffffffffu, mx1, 2));

            const float mn0 = fmaxf(m0r, mx0), mn1 = fmaxf(m1r, mx1);
            const float a0 = ex2(m0r - mn0), a1 = ex2(m1r - mn1);
            m0r = mn0; m1r = mn1;

            float rs0 = 0.0f, rs1 = 0.0f;
#pragma unroll
            for (int nt = 0; nt < 8; nt++) {
                s[nt][0] = ex2(s[nt][0] - mn0); s[nt][1] = ex2(s[nt][1] - mn0);
                s[nt][2] = ex2(s[nt][2] - mn1); s[nt][3] = ex2(s[nt][3] - mn1);
                rs0 += s[nt][0] + s[nt][1];
                rs1 += s[nt][2] + s[nt][3];
            }
            l0r = l0r * a0 + rs0;
            l1r = l1r * a1 + rs1;

#pragma unroll
            for (int nt = 0; nt < 8; nt++) {
                o[nt][0] *= a0; o[nt][1] *= a0;
                o[nt][2] *= a1; o[nt][3] *= a1;
            }

#pragma unroll
            for (int kt = 0; kt < 4; kt++) {
                uint32_t pf[4];
                pf[0] = pack_h2(s[2 * kt][0],     s[2 * kt][1]);
                pf[1] = pack_h2(s[2 * kt][2],     s[2 * kt][3]);
                pf[2] = pack_h2(s[2 * kt + 1][0], s[2 * kt + 1][1]);
                pf[3] = pack_h2(s[2 * kt + 1][2], s[2 * kt + 1][3]);

                const uint32_t va = kvb + F_T + koff
                    + (uint32_t)(kt * 16 + (lane & 15)) * KROWB + 16 * (lane >> 4);
#pragma unroll
                for (int ntp = 0; ntp < 4; ntp++) {
                    uint32_t vf[4];
                    ldm_x4t(vf, va + ntp * 32);
                    mma_f16(o[2 * ntp],     pf, vf[0], vf[1]);
                    mma_f16(o[2 * ntp + 1], pf, vf[2], vf[3]);
                }
            }
        }
    }

    l0r += __shfl_xor_sync(0xffffffffu, l0r, 1);
    l0r += __shfl_xor_sync(0xffffffffu, l0r, 2);
    l1r += __shfl_xor_sync(0xffffffffu, l1r, 1);
    l1r += __shfl_xor_sync(0xffffffffu, l1r, 2);

    const float inv0 = 1.0f / l0r, inv1 = 1.0f / l1r;
    const int gr = lane >> 2, gc = (lane & 3) * 2;
    const size_t row0 = (size_t)(b * SEQ + q0 + wid * 16 + gr) * EMBED + h * HD;
    const size_t row1 = row0 + 8 * EMBED;
#pragma unroll
    for (int nt = 0; nt < 8; nt++) {
        const int d = nt * 8 + gc;
        *(uint32_t*)(oo + row0 + d) = pack_h2(o[nt][0] * inv0, o[nt][1] * inv0);
        *(uint32_t*)(oo + row1 + d) = pack_h2(o[nt][2] * inv1, o[nt][3] * inv1);
    }
}

// ---------------------------------------------------------------------------
extern "C" void kernel_launch(void* const* d_in, const int* in_sizes, int n_in,
                              void* d_out, int out_size)
{
    const float* x     = (const float*)d_in[0];
    const float* W_qkv = (const float*)d_in[1];
    const float* b_qkv = (const float*)d_in[2];
    const float* W_p   = (const float*)d_in[3];
    const float* b_p   = (const float*)d_in[4];
    float* out = (float*)d_out;

    __half *xh, *wq, *wp, *at, *q, *k, *v;
    cudaGetSymbolAddress((void**)&xh, g_x);
    cudaGetSymbolAddress((void**)&wq, g_wqkv);
    cudaGetSymbolAddress((void**)&wp, g_wp);
    cudaGetSymbolAddress((void**)&at, g_at);
    cudaGetSymbolAddress((void**)&q,  g_q);
    cudaGetSymbolAddress((void**)&k,  g_k);
    cudaGetSymbolAddress((void**)&v,  g_v);

    cudaFuncSetAttribute(gemm_f16<0>, cudaFuncAttributeMaxDynamicSharedMemorySize, G_SMEM);
    cudaFuncSetAttribute(gemm_f16<1>, cudaFuncAttributeMaxDynamicSharedMemorySize, G_SMEM);
    cudaFuncSetAttribute(flash_f16,   cudaFuncAttributeMaxDynamicSharedMemorySize, F_SMEM);

    // all conversions in one launch
    {
        int total = NX4 + NQ4 + NP4;
        tohalf_all<<<(total + 255) / 256, 256>>>(
            (const float4*)x, (const float4*)W_qkv, (const float4*)W_p);
    }

    // QKV projection -> per-head q/k/v
    gemm_f16<1><<<dim3(QKV_N / 128, TOKENS / 128), 256, G_SMEM>>>(
        xh, wq, b_qkv, nullptr, TOKENS, QKV_N, EMBED);

    // attention (fine-grained grid: 1024 CTAs)
    flash_f16<<<dim3(SEQ / BQ, NHEAD, BATCH), 128, F_SMEM>>>(q, k, v, at);

    // output projection
    gemm_f16<0><<<dim3(EMBED / 128, TOKENS / 128), 256, G_SMEM>>>(
        at, wp, b_p, out, TOKENS, EMBED, EMBED);
}

// round 16
// speedup vs baseline: 1.0261x; 1.0261x over previous
#include <cuda_runtime.h>
#include <cuda_fp16.h>
#include <math.h>
#include <stdint.h>

#define EMBED   1024
#define NHEAD   16
#define HD      64
#define BATCH   2
#define SEQ     2048
#define TOKENS  (BATCH * SEQ)      // 4096
#define QKV_N   (3 * EMBED)        // 3072

// ---------------------------------------------------------------------------
// Scratch
// ---------------------------------------------------------------------------
__device__ __half g_x  [(size_t)TOKENS * EMBED];
__device__ __half g_wqkv[(size_t)QKV_N * EMBED];
__device__ __half g_wp [(size_t)EMBED * EMBED];
__device__ __half g_at [(size_t)TOKENS * EMBED];
#define HEADELEMS ((size_t)BATCH * NHEAD * SEQ * HD)
__device__ __half g_q[HEADELEMS], g_k[HEADELEMS], g_v[HEADELEMS];

// ---------------------------------------------------------------------------
// helpers
// ---------------------------------------------------------------------------
__device__ __forceinline__ uint32_t smem_u32(const void* p) {
    uint32_t a;
    asm("{ .reg .u64 t; cvta.to.shared.u64 t, %1; cvt.u32.u64 %0, t; }"
        : "=r"(a) : "l"(p));
    return a;
}
__device__ __forceinline__ void cp_async16(uint32_t s, const void* g) {
    asm volatile("cp.async.cg.shared.global [%0], [%1], 16;" :: "r"(s), "l"(g));
}
#define CP_COMMIT() asm volatile("cp.async.commit_group;" ::: "memory")
#define CP_WAIT1()  asm volatile("cp.async.wait_group 1;" ::: "memory")
#define CP_WAIT0()  asm volatile("cp.async.wait_group 0;" ::: "memory")

__device__ __forceinline__ void ldm_x4(uint32_t* r, uint32_t addr) {
    asm volatile("ldmatrix.sync.aligned.m8n8.x4.shared.b16 {%0,%1,%2,%3}, [%4];"
                 : "=r"(r[0]), "=r"(r[1]), "=r"(r[2]), "=r"(r[3]) : "r"(addr));
}
__device__ __forceinline__ void ldm_x4t(uint32_t* r, uint32_t addr) {
    asm volatile("ldmatrix.sync.aligned.m8n8.x4.trans.shared.b16 {%0,%1,%2,%3}, [%4];"
                 : "=r"(r[0]), "=r"(r[1]), "=r"(r[2]), "=r"(r[3]) : "r"(addr));
}
__device__ __forceinline__ void mma_f16(float* c, const uint32_t* a,
                                        uint32_t b0, uint32_t b1) {
    asm volatile("mma.sync.aligned.m16n8k16.row.col.f32.f16.f16.f32 "
                 "{%0,%1,%2,%3}, {%4,%5,%6,%7}, {%8,%9}, {%0,%1,%2,%3};"
                 : "+f"(c[0]), "+f"(c[1]), "+f"(c[2]), "+f"(c[3])
                 : "r"(a[0]), "r"(a[1]), "r"(a[2]), "r"(a[3]), "r"(b0), "r"(b1));
}
__device__ __forceinline__ uint32_t pack_h2(float x, float y) {
    __half2 v = __floats2half2_rn(x, y);
    return *(uint32_t*)&v;
}
__device__ __forceinline__ float ex2(float x) {
    float r; asm("ex2.approx.f32 %0, %1;" : "=f"(r) : "f"(x)); return r;
}

// ---------------------------------------------------------------------------
// fp32 -> fp16 for all three inputs in one launch
// ---------------------------------------------------------------------------
#define NX4 (TOKENS * EMBED / 4)
#define NQ4 (QKV_N * EMBED / 4)
#define NP4 (EMBED * EMBED / 4)

__global__ void tohalf_all(const float4* __restrict__ x,
                           const float4* __restrict__ wq,
                           const float4* __restrict__ wp)
{
    int i = blockIdx.x * blockDim.x + threadIdx.x;
    const float4* src;
    uint32_t* dst;
    int j;
    if (i < NX4)                 { src = x;  dst = (uint32_t*)g_x;    j = i; }
    else if (i < NX4 + NQ4)      { src = wq; dst = (uint32_t*)g_wqkv; j = i - NX4; }
    else if (i < NX4 + NQ4 + NP4){ src = wp; dst = (uint32_t*)g_wp;   j = i - NX4 - NQ4; }
    else return;
    float4 v = src[j];
    dst[2 * j + 0] = pack_h2(v.x, v.y);
    dst[2 * j + 1] = pack_h2(v.z, v.w);
}

// ---------------------------------------------------------------------------
// HMMA fp16 GEMM: CTA 128x128, BK=64 (16 chunks), 8 warps (64x32 warptile),
// 3-stage cp.async, 1 sync per chunk. Rows padded to 144B.
// MODE 0: fp32 C + bias.
// MODE 1: QKV epilogue — stage C tile in smem, coalesced fp16 writes to
//         per-head q (* 0.125*log2e, for base-2 softmax)/k/v.
// ---------------------------------------------------------------------------
#define GROWB  144
#define GTILE  (128 * GROWB)   // 18432
#define GSTG   (2 * GTILE)     // 36864 (A + B)
#define G_SMEM (3 * GSTG)      // 110592
#define CROW   272             // staging row bytes (128 fp16 + 16B pad)

template <int MODE>
__global__ __launch_bounds__(256)
void gemm_f16(const __half* __restrict__ A, const __half* __restrict__ B,
              const float* __restrict__ bias, float* __restrict__ C,
              int M, int N, int K)
{
    extern __shared__ char smem[];
    const uint32_t sb = smem_u32(smem);
    const int tid  = threadIdx.x;
    const int wid  = tid >> 5;
    const int lane = tid & 31;
    const int warp_m = wid & 1;
    const int warp_n = wid >> 1;
    const int m0 = blockIdx.y * 128;
    const int n0 = blockIdx.x * 128;

    const __half* gA = A + (size_t)m0 * K;
    const __half* gB = B + (size_t)n0 * K;

    float acc[4][4][4];
#pragma unroll
    for (int i = 0; i < 4; i++)
#pragma unroll
        for (int j = 0; j < 4; j++)
#pragma unroll
            for (int f = 0; f < 4; f++) acc[i][j][f] = 0.0f;

    const int nk = K >> 6;   // BK = 64

    // preload chunk 0 -> stage 0 (2048 x 16B chunks, 8 per thread)
    {
        uint32_t sT = sb;
#pragma unroll
        for (int i = 0; i < 8; i++) {
            int chunk = tid + i * 256;
            int tile = chunk >> 10;
            int r = (chunk >> 3) & 127;
            int col = (chunk & 7) * 16;
            const __half* src = tile ? gB : gA;
            cp_async16(sT + tile * GTILE + r * GROWB + col,
                       (const char*)(src + (size_t)r * K) + col);
        }
    }
    CP_COMMIT();

    const uint32_t a_off = (uint32_t)(warp_m * 64 + (lane & 15)) * GROWB + (lane >> 4) * 16;
    const uint32_t b_off = (uint32_t)(warp_n * 32 + (lane & 15)) * GROWB + (lane >> 4) * 16;

    int buf = 0, nxt = 1;
    for (int c = 0; c < nk; c++) {
        if (c + 1 < nk) {
            const int kb = (c + 1) * 128;
            uint32_t sT = sb + nxt * GSTG;
#pragma unroll
            for (int i = 0; i < 8; i++) {
                int chunk = tid + i * 256;
                int tile = chunk >> 10;
                int r = (chunk >> 3) & 127;
                int col = (chunk & 7) * 16;
                const __half* src = tile ? gB : gA;
                cp_async16(sT + tile * GTILE + r * GROWB + col,
                           (const char*)(src + (size_t)r * K) + kb + col);
            }
            CP_COMMIT();
            CP_WAIT1();
        } else {
            CP_WAIT0();
        }
        __syncthreads();

        const uint32_t st = sb + buf * GSTG;
#pragma unroll
        for (int ks = 0; ks < 4; ks++) {
            const uint32_t ko = ks * 32;
            uint32_t af[4][4], bf[2][4];
#pragma unroll
            for (int mt = 0; mt < 4; mt++)
                ldm_x4(af[mt], st + a_off + mt * 16 * GROWB + ko);
#pragma unroll
            for (int bt = 0; bt < 2; bt++)
                ldm_x4(bf[bt], st + GTILE + b_off + bt * 16 * GROWB + ko);
#pragma unroll
            for (int mt = 0; mt < 4; mt++)
#pragma unroll
                for (int nt = 0; nt < 4; nt++) {
                    const int bt = nt >> 1, p = nt & 1;
                    mma_f16(acc[mt][nt], af[mt], bf[bt][p], bf[bt][p + 2]);
                }
        }
        buf = nxt; nxt = nxt + 1 == 3 ? 0 : nxt + 1;
    }

    const int gr = lane >> 2;
    const int gc = (lane & 3) << 1;

    if (MODE == 0) {
#pragma unroll
        for (int mt = 0; mt < 4; mt++) {
            const int row = m0 + warp_m * 64 + mt * 16 + gr;
#pragma unroll
            for (int nt = 0; nt < 4; nt++) {
                const int col = n0 + warp_n * 32 + nt * 8 + gc;
                const float b0 = bias[col], b1 = bias[col + 1];
                *(float2*)(C + (size_t)row * N + col) =
                    make_float2(acc[mt][nt][0] + b0, acc[mt][nt][1] + b1);
                *(float2*)(C + (size_t)(row + 8) * N + col) =
                    make_float2(acc[mt][nt][2] + b0, acc[mt][nt][3] + b1);
            }
        }
    } else {
        __syncthreads();   // mainloop smem dead
        const float sc = (n0 >> 10) == 0 ? 0.125f * 1.44269504f : 1.0f;
#pragma unroll
        for (int mt = 0; mt < 4; mt++) {
            const int r0l = warp_m * 64 + mt * 16 + gr;
#pragma unroll
            for (int nt = 0; nt < 4; nt++) {
                const int cl = warp_n * 32 + nt * 8 + gc;
                const float b0 = bias[n0 + cl], b1 = bias[n0 + cl + 1];
                *(uint32_t*)(smem + r0l * CROW + cl * 2) =
                    pack_h2((acc[mt][nt][0] + b0) * sc, (acc[mt][nt][1] + b1) * sc);
                *(uint32_t*)(smem + (r0l + 8) * CROW + cl * 2) =
                    pack_h2((acc[mt][nt][2] + b0) * sc, (acc[mt][nt][3] + b1) * sc);
            }
        }
        __syncthreads();

        const int t = n0 >> 10;   // 0=q 1=k 2=v
        __half* dp = t == 0 ? g_q : (t == 1 ? g_k : g_v);
        const int bb  = m0 >> 11;
        const int sq0 = m0 & (SEQ - 1);
        const int j = tid & 7;
#pragma unroll
        for (int ch = 0; ch < 2; ch++) {
            const int hh = ((n0 + ch * 64) >> 6) & (NHEAD - 1);
            const size_t base = (((size_t)(bb * NHEAD + hh)) * SEQ + sq0) * HD;
#pragma unroll
            for (int it = 0; it < 4; it++) {
                const int row = (tid >> 3) + it * 32;
                uint4 v = *(const uint4*)(smem + row * CROW + ch * 128 + j * 16);
                *(uint4*)((char*)(dp + base + (size_t)row * HD) + j * 16) = v;
            }
        }
    }
}

// ---------------------------------------------------------------------------
// HMMA flash attention: 8 warps x 16 q-rows; direct-GMEM Q fragments;
// 3-stage KV pipeline (BKV=128), 1 sync/tile, 2 CTAs/SM; base-2 softmax;
// l-sum kept lane-local, reduced once at epilogue.
// ---------------------------------------------------------------------------
#define BQ     128
#define BKV    128
#define KROWB  144
#define F_T    (BKV * KROWB)       // 18432
#define F_STG  (2 * F_T)           // 36864
#define F_SMEM (3 * F_STG)         // 110592
#define NKV    (SEQ / BKV)         // 16

__global__ __launch_bounds__(256, 2)
void flash_f16(const __half* __restrict__ qq, const __half* __restrict__ kk,
               const __half* __restrict__ vv, __half* __restrict__ oo)
{
    extern __shared__ char smem[];
    const uint32_t sb = smem_u32(smem);
    const int tid = threadIdx.x;
    const int wid = tid >> 5;
    const int lane = tid & 31;

    const int q0 = blockIdx.x * BQ;
    const int h  = blockIdx.y;
    const int b  = blockIdx.z;
    const size_t hoff = ((size_t)(b * NHEAD + h)) * SEQ * HD;

    // KV tile 0 -> stage 0
#pragma unroll
    for (int i = 0; i < 8; i++) {
        int chunk = tid + i * 256;
        int tensor = chunk >> 10;
        int row = (chunk >> 3) & 127;
        int col = (chunk & 7) * 16;
        const __half* src = tensor ? vv : kk;
        cp_async16(sb + tensor * F_T + row * KROWB + col,
                   (const char*)(src + hoff + (size_t)row * HD) + col);
    }
    CP_COMMIT();

    // Q fragments directly from GMEM
    uint32_t qf[4][4];
    {
        const int r  = wid * 16 + (lane >> 2);
        const int c  = (lane & 3) * 2;
        const __half* q_r0 = qq + hoff + (size_t)(q0 + r) * HD;
        const __half* q_r1 = q_r0 + 8 * HD;
#pragma unroll
        for (int kt = 0; kt < 4; kt++) {
            qf[kt][0] = *(const uint32_t*)(q_r0 + kt * 16 + c);
            qf[kt][1] = *(const uint32_t*)(q_r1 + kt * 16 + c);
            qf[kt][2] = *(const uint32_t*)(q_r0 + kt * 16 + c + 8);
            qf[kt][3] = *(const uint32_t*)(q_r1 + kt * 16 + c + 8);
        }
    }

    float o[8][4];
#pragma unroll
    for (int nt = 0; nt < 8; nt++)
#pragma unroll
        for (int f = 0; f < 4; f++) o[nt][f] = 0.0f;
    float m0r = -INFINITY, m1r = -INFINITY;
    float l0r = 0.0f, l1r = 0.0f;   // lane-local partials

    int buf = 0, nxt = 1;
    for (int t = 0; t < NKV; t++) {
        if (t + 1 < NKV) {
            const int key0 = (t + 1) * BKV;
            const uint32_t dstb = sb + nxt * F_STG;
#pragma unroll
            for (int i = 0; i < 8; i++) {
                int chunk = tid + i * 256;
                int tensor = chunk >> 10;
                int row = (chunk >> 3) & 127;
                int col = (chunk & 7) * 16;
                const __half* src = tensor ? vv : kk;
                cp_async16(dstb + tensor * F_T + row * KROWB + col,
                           (const char*)(src + hoff + (size_t)(key0 + row) * HD) + col);
            }
            CP_COMMIT();
            CP_WAIT1();
        } else {
            CP_WAIT0();
        }
        __syncthreads();

        const uint32_t kvb = sb + buf * F_STG;

#pragma unroll
        for (int sub = 0; sub < 2; sub++) {
            const uint32_t koff = (uint32_t)(sub * 64) * KROWB;

            float s[8][4];
#pragma unroll
            for (int nt = 0; nt < 8; nt++)
#pragma unroll
                for (int f = 0; f < 4; f++) s[nt][f] = 0.0f;

#pragma unroll
            for (int ntp = 0; ntp < 4; ntp++) {
                const uint32_t ka = kvb + koff
                    + (uint32_t)(ntp * 16 + (lane & 15)) * KROWB + 16 * (lane >> 4);
#pragma unroll
                for (int kt = 0; kt < 4; kt++) {
                    uint32_t kf[4];
                    ldm_x4(kf, ka + kt * 32);
                    mma_f16(s[2 * ntp],     qf[kt], kf[0], kf[2]);
                    mma_f16(s[2 * ntp + 1], qf[kt], kf[1], kf[3]);
                }
            }

            // online softmax in base-2; max needs 4-lane reduce, l doesn't
            float mx0 = -INFINITY, mx1 = -INFINITY;
#pragma unroll
            for (int nt = 0; nt < 8; nt++) {
                mx0 = fmaxf(mx0, fmaxf(s[nt][0], s[nt][1]));
                mx1 = fmaxf(mx1, fmaxf(s[nt][2], s[nt][3]));
            }
            mx0 = fmaxf(mx0, __shfl_xor_sync(0xffffffffu, mx0, 1));
            mx0 = fmaxf(mx0, __shfl_xor_sync(0xffffffffu, mx0, 2));
            mx1 = fmaxf(mx1, __shfl_xor_sync(0xffffffffu, mx1, 1));
            mx1 = fmaxf(mx1, __shfl_xor_sync(0xffffffffu, mx1, 2));

            const float mn0 = fmaxf(m0r, mx0), mn1 = fmaxf(m1r, mx1);
            const float a0 = ex2(m0r - mn0), a1 = ex2(m1r - mn1);
            m0r = mn0; m1r = mn1;

            float rs0 = 0.0f, rs1 = 0.0f;
#pragma unroll
            for (int nt = 0; nt < 8; nt++) {
                s[nt][0] = ex2(s[nt][0] - mn0); s[nt][1] = ex2(s[nt][1] - mn0);
                s[nt][2] = ex2(s[nt][2] - mn1); s[nt][3] = ex2(s[nt][3] - mn1);
                rs0 += s[nt][0] + s[nt][1];
                rs1 += s[nt][2] + s[nt][3];
            }
            l0r = l0r * a0 + rs0;   // lane-local; reduced at epilogue
            l1r = l1r * a1 + rs1;

#pragma unroll
            for (int nt = 0; nt < 8; nt++) {
                o[nt][0] *= a0; o[nt][1] *= a0;
                o[nt][2] *= a1; o[nt][3] *= a1;
            }

            // O += P V
#pragma unroll
            for (int kt = 0; kt < 4; kt++) {
                uint32_t pf[4];
                pf[0] = pack_h2(s[2 * kt][0],     s[2 * kt][1]);
                pf[1] = pack_h2(s[2 * kt][2],     s[2 * kt][3]);
                pf[2] = pack_h2(s[2 * kt + 1][0], s[2 * kt + 1][1]);
                pf[3] = pack_h2(s[2 * kt + 1][2], s[2 * kt + 1][3]);

                const uint32_t va = kvb + F_T + koff
                    + (uint32_t)(kt * 16 + (lane & 15)) * KROWB + 16 * (lane >> 4);
#pragma unroll
                for (int ntp = 0; ntp < 4; ntp++) {
                    uint32_t vf[4];
                    ldm_x4t(vf, va + ntp * 32);
                    mma_f16(o[2 * ntp],     pf, vf[0], vf[1]);
                    mma_f16(o[2 * ntp + 1], pf, vf[2], vf[3]);
                }
            }
        }
        buf = nxt; nxt = nxt + 1 == 3 ? 0 : nxt + 1;
    }

    // final l reduction
    l0r += __shfl_xor_sync(0xffffffffu, l0r, 1);
    l0r += __shfl_xor_sync(0xffffffffu, l0r, 2);
    l1r += __shfl_xor_sync(0xffffffffu, l1r, 1);
    l1r += __shfl_xor_sync(0xffffffffu, l1r, 2);

    const float inv0 = 1.0f / l0r, inv1 = 1.0f / l1r;
    const int gr = lane >> 2, gc = (lane & 3) * 2;
    const size_t row0 = (size_t)(b * SEQ + q0 + wid * 16 + gr) * EMBED + h * HD;
    const size_t row1 = row0 + 8 * EMBED;
#pragma unroll
    for (int nt = 0; nt < 8; nt++) {
        const int d = nt * 8 + gc;
        *(uint32_t*)(oo + row0 + d) = pack_h2(o[nt][0] * inv0, o[nt][1] * inv0);
        *(uint32_t*)(oo + row1 + d) = pack_h2(o[nt][2] * inv1, o[nt][3] * inv1);
    }
}

// ---------------------------------------------------------------------------
extern "C" void kernel_launch(void* const* d_in, const int* in_sizes, int n_in,
                              void* d_out, int out_size)
{
    const float* x     = (const float*)d_in[0];
    const float* W_qkv = (const float*)d_in[1];
    const float* b_qkv = (const float*)d_in[2];
    const float* W_p   = (const float*)d_in[3];
    const float* b_p   = (const float*)d_in[4];
    float* out = (float*)d_out;

    __half *xh, *wq, *wp, *at, *q, *k, *v;
    cudaGetSymbolAddress((void**)&xh, g_x);
    cudaGetSymbolAddress((void**)&wq, g_wqkv);
    cudaGetSymbolAddress((void**)&wp, g_wp);
    cudaGetSymbolAddress((void**)&at, g_at);
    cudaGetSymbolAddress((void**)&q,  g_q);
    cudaGetSymbolAddress((void**)&k,  g_k);
    cudaGetSymbolAddress((void**)&v,  g_v);

    cudaFuncSetAttribute(gemm_f16<0>, cudaFuncAttributeMaxDynamicSharedMemorySize, G_SMEM);
    cudaFuncSetAttribute(gemm_f16<1>, cudaFuncAttributeMaxDynamicSharedMemorySize, G_SMEM);
    cudaFuncSetAttribute(flash_f16,   cudaFuncAttributeMaxDynamicSharedMemorySize, F_SMEM);

    // all conversions in one launch
    {
        int total = NX4 + NQ4 + NP4;
        tohalf_all<<<(total + 255) / 256, 256>>>(
            (const float4*)x, (const float4*)W_qkv, (const float4*)W_p);
    }

    // QKV projection -> per-head q/k/v
    gemm_f16<1><<<dim3(QKV_N / 128, TOKENS / 128), 256, G_SMEM>>>(
        xh, wq, b_qkv, nullptr, TOKENS, QKV_N, EMBED);

    // attention
    flash_f16<<<dim3(SEQ / BQ, NHEAD, BATCH), 256, F_SMEM>>>(q, k, v, at);

    // output projection
    gemm_f16<0><<<dim3(EMBED / 128, TOKENS / 128), 256, G_SMEM>>>(
        at, wp, b_p, out, TOKENS, EMBED, EMBED);
}

// round 17
// speedup vs baseline: 1.0316x; 1.0053x over previous
#include <cuda_runtime.h>
#include <cuda_fp16.h>
#include <math.h>
#include <stdint.h>

#define EMBED   1024
#define NHEAD   16
#define HD      64
#define BATCH   2
#define SEQ     2048
#define TOKENS  (BATCH * SEQ)      // 4096
#define QKV_N   (3 * EMBED)        // 3072

// ---------------------------------------------------------------------------
// Scratch
// ---------------------------------------------------------------------------
__device__ __half g_x  [(size_t)TOKENS * EMBED];
__device__ __half g_wqkv[(size_t)QKV_N * EMBED];
__device__ __half g_wp [(size_t)EMBED * EMBED];
__device__ __half g_at [(size_t)TOKENS * EMBED];
#define HEADELEMS ((size_t)BATCH * NHEAD * SEQ * HD)
__device__ __half g_q[HEADELEMS], g_k[HEADELEMS], g_v[HEADELEMS];

// ---------------------------------------------------------------------------
// helpers
// ---------------------------------------------------------------------------
__device__ __forceinline__ uint32_t smem_u32(const void* p) {
    uint32_t a;
    asm("{ .reg .u64 t; cvta.to.shared.u64 t, %1; cvt.u32.u64 %0, t; }"
        : "=r"(a) : "l"(p));
    return a;
}
__device__ __forceinline__ void cp_async16(uint32_t s, const void* g) {
    asm volatile("cp.async.cg.shared.global [%0], [%1], 16;" :: "r"(s), "l"(g));
}
#define CP_COMMIT() asm volatile("cp.async.commit_group;" ::: "memory")
#define CP_WAIT1()  asm volatile("cp.async.wait_group 1;" ::: "memory")
#define CP_WAIT0()  asm volatile("cp.async.wait_group 0;" ::: "memory")

__device__ __forceinline__ void ldm_x4(uint32_t* r, uint32_t addr) {
    asm volatile("ldmatrix.sync.aligned.m8n8.x4.shared.b16 {%0,%1,%2,%3}, [%4];"
                 : "=r"(r[0]), "=r"(r[1]), "=r"(r[2]), "=r"(r[3]) : "r"(addr));
}
__device__ __forceinline__ void ldm_x4t(uint32_t* r, uint32_t addr) {
    asm volatile("ldmatrix.sync.aligned.m8n8.x4.trans.shared.b16 {%0,%1,%2,%3}, [%4];"
                 : "=r"(r[0]), "=r"(r[1]), "=r"(r[2]), "=r"(r[3]) : "r"(addr));
}
__device__ __forceinline__ void mma_f16(float* c, const uint32_t* a,
                                        uint32_t b0, uint32_t b1) {
    asm volatile("mma.sync.aligned.m16n8k16.row.col.f32.f16.f16.f32 "
                 "{%0,%1,%2,%3}, {%4,%5,%6,%7}, {%8,%9}, {%0,%1,%2,%3};"
                 : "+f"(c[0]), "+f"(c[1]), "+f"(c[2]), "+f"(c[3])
                 : "r"(a[0]), "r"(a[1]), "r"(a[2]), "r"(a[3]), "r"(b0), "r"(b1));
}
__device__ __forceinline__ uint32_t pack_h2(float x, float y) {
    __half2 v = __floats2half2_rn(x, y);
    return *(uint32_t*)&v;
}
__device__ __forceinline__ float ex2(float x) {
    float r; asm("ex2.approx.f32 %0, %1;" : "=f"(r) : "f"(x)); return r;
}

// ---------------------------------------------------------------------------
// fp32 -> fp16 for all three inputs in one launch
// ---------------------------------------------------------------------------
#define NX4 (TOKENS * EMBED / 4)
#define NQ4 (QKV_N * EMBED / 4)
#define NP4 (EMBED * EMBED / 4)

__global__ void tohalf_all(const float4* __restrict__ x,
                           const float4* __restrict__ wq,
                           const float4* __restrict__ wp)
{
    int i = blockIdx.x * blockDim.x + threadIdx.x;
    const float4* src;
    uint32_t* dst;
    int j;
    if (i < NX4)                 { src = x;  dst = (uint32_t*)g_x;    j = i; }
    else if (i < NX4 + NQ4)      { src = wq; dst = (uint32_t*)g_wqkv; j = i - NX4; }
    else if (i < NX4 + NQ4 + NP4){ src = wp; dst = (uint32_t*)g_wp;   j = i - NX4 - NQ4; }
    else return;
    float4 v = src[j];
    dst[2 * j + 0] = pack_h2(v.x, v.y);
    dst[2 * j + 1] = pack_h2(v.z, v.w);
}

// ---------------------------------------------------------------------------
// HMMA fp16 GEMM: CTA 128x128, BK=64 (16 chunks), 8 warps (64x32 warptile),
// 3-stage cp.async, 1 sync per chunk. Rows padded to 144B.
// MODE 0: fp32 C + bias.
// MODE 1: QKV epilogue — stage C tile in smem, coalesced fp16 writes to
//         per-head q (* 0.125*log2e, for base-2 softmax)/k/v.
// ---------------------------------------------------------------------------
#define GROWB  144
#define GTILE  (128 * GROWB)   // 18432
#define GSTG   (2 * GTILE)     // 36864 (A + B)
#define G_SMEM (3 * GSTG)      // 110592
#define CROW   272             // staging row bytes (128 fp16 + 16B pad)

template <int MODE>
__global__ __launch_bounds__(256)
void gemm_f16(const __half* __restrict__ A, const __half* __restrict__ B,
              const float* __restrict__ bias, float* __restrict__ C,
              int M, int N, int K)
{
    extern __shared__ char smem[];
    const uint32_t sb = smem_u32(smem);
    const int tid  = threadIdx.x;
    const int wid  = tid >> 5;
    const int lane = tid & 31;
    const int warp_m = wid & 1;
    const int warp_n = wid >> 1;
    const int m0 = blockIdx.y * 128;
    const int n0 = blockIdx.x * 128;

    const __half* gA = A + (size_t)m0 * K;
    const __half* gB = B + (size_t)n0 * K;

    float acc[4][4][4];
#pragma unroll
    for (int i = 0; i < 4; i++)
#pragma unroll
        for (int j = 0; j < 4; j++)
#pragma unroll
            for (int f = 0; f < 4; f++) acc[i][j][f] = 0.0f;

    const int nk = K >> 6;   // BK = 64

    // preload chunk 0 -> stage 0 (2048 x 16B chunks, 8 per thread)
    {
        uint32_t sT = sb;
#pragma unroll
        for (int i = 0; i < 8; i++) {
            int chunk = tid + i * 256;
            int tile = chunk >> 10;
            int r = (chunk >> 3) & 127;
            int col = (chunk & 7) * 16;
            const __half* src = tile ? gB : gA;
            cp_async16(sT + tile * GTILE + r * GROWB + col,
                       (const char*)(src + (size_t)r * K) + col);
        }
    }
    CP_COMMIT();

    const uint32_t a_off = (uint32_t)(warp_m * 64 + (lane & 15)) * GROWB + (lane >> 4) * 16;
    const uint32_t b_off = (uint32_t)(warp_n * 32 + (lane & 15)) * GROWB + (lane >> 4) * 16;

    int buf = 0, nxt = 1;
    for (int c = 0; c < nk; c++) {
        if (c + 1 < nk) {
            const int kb = (c + 1) * 128;
            uint32_t sT = sb + nxt * GSTG;
#pragma unroll
            for (int i = 0; i < 8; i++) {
                int chunk = tid + i * 256;
                int tile = chunk >> 10;
                int r = (chunk >> 3) & 127;
                int col = (chunk & 7) * 16;
                const __half* src = tile ? gB : gA;
                cp_async16(sT + tile * GTILE + r * GROWB + col,
                           (const char*)(src + (size_t)r * K) + kb + col);
            }
            CP_COMMIT();
            CP_WAIT1();
        } else {
            CP_WAIT0();
        }
        __syncthreads();

        const uint32_t st = sb + buf * GSTG;
#pragma unroll
        for (int ks = 0; ks < 4; ks++) {
            const uint32_t ko = ks * 32;
            uint32_t af[4][4], bf[2][4];
#pragma unroll
            for (int mt = 0; mt < 4; mt++)
                ldm_x4(af[mt], st + a_off + mt * 16 * GROWB + ko);
#pragma unroll
            for (int bt = 0; bt < 2; bt++)
                ldm_x4(bf[bt], st + GTILE + b_off + bt * 16 * GROWB + ko);
#pragma unroll
            for (int mt = 0; mt < 4; mt++)
#pragma unroll
                for (int nt = 0; nt < 4; nt++) {
                    const int bt = nt >> 1, p = nt & 1;
                    mma_f16(acc[mt][nt], af[mt], bf[bt][p], bf[bt][p + 2]);
                }
        }
        buf = nxt; nxt = nxt + 1 == 3 ? 0 : nxt + 1;
    }

    const int gr = lane >> 2;
    const int gc = (lane & 3) << 1;

    if (MODE == 0) {
#pragma unroll
        for (int mt = 0; mt < 4; mt++) {
            const int row = m0 + warp_m * 64 + mt * 16 + gr;
#pragma unroll
            for (int nt = 0; nt < 4; nt++) {
                const int col = n0 + warp_n * 32 + nt * 8 + gc;
                const float b0 = bias[col], b1 = bias[col + 1];
                *(float2*)(C + (size_t)row * N + col) =
                    make_float2(acc[mt][nt][0] + b0, acc[mt][nt][1] + b1);
                *(float2*)(C + (size_t)(row + 8) * N + col) =
                    make_float2(acc[mt][nt][2] + b0, acc[mt][nt][3] + b1);
            }
        }
    } else {
        __syncthreads();   // mainloop smem dead
        const float sc = (n0 >> 10) == 0 ? 0.125f * 1.44269504f : 1.0f;
#pragma unroll
        for (int mt = 0; mt < 4; mt++) {
            const int r0l = warp_m * 64 + mt * 16 + gr;
#pragma unroll
            for (int nt = 0; nt < 4; nt++) {
                const int cl = warp_n * 32 + nt * 8 + gc;
                const float b0 = bias[n0 + cl], b1 = bias[n0 + cl + 1];
                *(uint32_t*)(smem + r0l * CROW + cl * 2) =
                    pack_h2((acc[mt][nt][0] + b0) * sc, (acc[mt][nt][1] + b1) * sc);
                *(uint32_t*)(smem + (r0l + 8) * CROW + cl * 2) =
                    pack_h2((acc[mt][nt][2] + b0) * sc, (acc[mt][nt][3] + b1) * sc);
            }
        }
        __syncthreads();

        const int t = n0 >> 10;   // 0=q 1=k 2=v
        __half* dp = t == 0 ? g_q : (t == 1 ? g_k : g_v);
        const int bb  = m0 >> 11;
        const int sq0 = m0 & (SEQ - 1);
        const int j = tid & 7;
#pragma unroll
        for (int ch = 0; ch < 2; ch++) {
            const int hh = ((n0 + ch * 64) >> 6) & (NHEAD - 1);
            const size_t base = (((size_t)(bb * NHEAD + hh)) * SEQ + sq0) * HD;
#pragma unroll
            for (int it = 0; it < 4; it++) {
                const int row = (tid >> 3) + it * 32;
                uint4 v = *(const uint4*)(smem + row * CROW + ch * 128 + j * 16);
                *(uint4*)((char*)(dp + base + (size_t)row * HD) + j * 16) = v;
            }
        }
    }
}

// ---------------------------------------------------------------------------
// HMMA flash attention: 8 warps x 16 q-rows; direct-GMEM Q fragments;
// 3-stage KV pipeline (BKV=128), 1 sync/tile, 2 CTAs/SM; base-2 softmax;
// l-sum kept lane-local, reduced once at epilogue.
// ---------------------------------------------------------------------------
#define BQ     128
#define BKV    128
#define KROWB  144
#define F_T    (BKV * KROWB)       // 18432
#define F_STG  (2 * F_T)           // 36864
#define F_SMEM (3 * F_STG)         // 110592
#define NKV    (SEQ / BKV)         // 16

__global__ __launch_bounds__(256, 2)
void flash_f16(const __half* __restrict__ qq, const __half* __restrict__ kk,
               const __half* __restrict__ vv, __half* __restrict__ oo)
{
    extern __shared__ char smem[];
    const uint32_t sb = smem_u32(smem);
    const int tid = threadIdx.x;
    const int wid = tid >> 5;
    const int lane = tid & 31;

    const int q0 = blockIdx.x * BQ;
    const int h  = blockIdx.y;
    const int b  = blockIdx.z;
    const size_t hoff = ((size_t)(b * NHEAD + h)) * SEQ * HD;

    // KV tile 0 -> stage 0
#pragma unroll
    for (int i = 0; i < 8; i++) {
        int chunk = tid + i * 256;
        int tensor = chunk >> 10;
        int row = (chunk >> 3) & 127;
        int col = (chunk & 7) * 16;
        const __half* src = tensor ? vv : kk;
        cp_async16(sb + tensor * F_T + row * KROWB + col,
                   (const char*)(src + hoff + (size_t)row * HD) + col);
    }
    CP_COMMIT();

    // Q fragments directly from GMEM
    uint32_t qf[4][4];
    {
        const int r  = wid * 16 + (lane >> 2);
        const int c  = (lane & 3) * 2;
        const __half* q_r0 = qq + hoff + (size_t)(q0 + r) * HD;
        const __half* q_r1 = q_r0 + 8 * HD;
#pragma unroll
        for (int kt = 0; kt < 4; kt++) {
            qf[kt][0] = *(const uint32_t*)(q_r0 + kt * 16 + c);
            qf[kt][1] = *(const uint32_t*)(q_r1 + kt * 16 + c);
            qf[kt][2] = *(const uint32_t*)(q_r0 + kt * 16 + c + 8);
            qf[kt][3] = *(const uint32_t*)(q_r1 + kt * 16 + c + 8);
        }
    }

    float o[8][4];
#pragma unroll
    for (int nt = 0; nt < 8; nt++)
#pragma unroll
        for (int f = 0; f < 4; f++) o[nt][f] = 0.0f;
    float m0r = -INFINITY, m1r = -INFINITY;
    float l0r = 0.0f, l1r = 0.0f;   // lane-local partials

    int buf = 0, nxt = 1;
    for (int t = 0; t < NKV; t++) {
        if (t + 1 < NKV) {
            const int key0 = (t + 1) * BKV;
            const uint32_t dstb = sb + nxt * F_STG;
#pragma unroll
            for (int i = 0; i < 8; i++) {
                int chunk = tid + i * 256;
                int tensor = chunk >> 10;
                int row = (chunk >> 3) & 127;
                int col = (chunk & 7) * 16;
                const __half* src = tensor ? vv : kk;
                cp_async16(dstb + tensor * F_T + row * KROWB + col,
                           (const char*)(src + hoff + (size_t)(key0 + row) * HD) + col);
            }
            CP_COMMIT();
            CP_WAIT1();
        } else {
            CP_WAIT0();
        }
        __syncthreads();

        const uint32_t kvb = sb + buf * F_STG;

#pragma unroll
        for (int sub = 0; sub < 2; sub++) {
            const uint32_t koff = (uint32_t)(sub * 64) * KROWB;

            float s[8][4];
#pragma unroll
            for (int nt = 0; nt < 8; nt++)
#pragma unroll
                for (int f = 0; f < 4; f++) s[nt][f] = 0.0f;

#pragma unroll
            for (int ntp = 0; ntp < 4; ntp++) {
                const uint32_t ka = kvb + koff
                    + (uint32_t)(ntp * 16 + (lane & 15)) * KROWB + 16 * (lane >> 4);
#pragma unroll
                for (int kt = 0; kt < 4; kt++) {
                    uint32_t kf[4];
                    ldm_x4(kf, ka + kt * 32);
                    mma_f16(s[2 * ntp],     qf[kt], kf[0], kf[2]);
                    mma_f16(s[2 * ntp + 1], qf[kt], kf[1], kf[3]);
                }
            }

            // online softmax in base-2; max needs 4-lane reduce, l doesn't
            float mx0 = -INFINITY, mx1 = -INFINITY;
#pragma unroll
            for (int nt = 0; nt < 8; nt++) {
                mx0 = fmaxf(mx0, fmaxf(s[nt][0], s[nt][1]));
                mx1 = fmaxf(mx1, fmaxf(s[nt][2], s[nt][3]));
            }
            mx0 = fmaxf(mx0, __shfl_xor_sync(0xffffffffu, mx0, 1));
            mx0 = fmaxf(mx0, __shfl_xor_sync(0xffffffffu, mx0, 2));
            mx1 = fmaxf(mx1, __shfl_xor_sync(0xffffffffu, mx1, 1));
            mx1 = fmaxf(mx1, __shfl_xor_sync(0xffffffffu, mx1, 2));

            const float mn0 = fmaxf(m0r, mx0), mn1 = fmaxf(m1r, mx1);
            const float a0 = ex2(m0r - mn0), a1 = ex2(m1r - mn1);
            m0r = mn0; m1r = mn1;

            float rs0 = 0.0f, rs1 = 0.0f;
#pragma unroll
            for (int nt = 0; nt < 8; nt++) {
                s[nt][0] = ex2(s[nt][0] - mn0); s[nt][1] = ex2(s[nt][1] - mn0);
                s[nt][2] = ex2(s[nt][2] - mn1); s[nt][3] = ex2(s[nt][3] - mn1);
                rs0 += s[nt][0] + s[nt][1];
                rs1 += s[nt][2] + s[nt][3];
            }
            l0r = l0r * a0 + rs0;   // lane-local; reduced at epilogue
            l1r = l1r * a1 + rs1;

#pragma unroll
            for (int nt = 0; nt < 8; nt++) {
                o[nt][0] *= a0; o[nt][1] *= a0;
                o[nt][2] *= a1; o[nt][3] *= a1;
            }

            // O += P V
#pragma unroll
            for (int kt = 0; kt < 4; kt++) {
                uint32_t pf[4];
                pf[0] = pack_h2(s[2 * kt][0],     s[2 * kt][1]);
                pf[1] = pack_h2(s[2 * kt][2],     s[2 * kt][3]);
                pf[2] = pack_h2(s[2 * kt + 1][0], s[2 * kt + 1][1]);
                pf[3] = pack_h2(s[2 * kt + 1][2], s[2 * kt + 1][3]);

                const uint32_t va = kvb + F_T + koff
                    + (uint32_t)(kt * 16 + (lane & 15)) * KROWB + 16 * (lane >> 4);
#pragma unroll
                for (int ntp = 0; ntp < 4; ntp++) {
                    uint32_t vf[4];
                    ldm_x4t(vf, va + ntp * 32);
                    mma_f16(o[2 * ntp],     pf, vf[0], vf[1]);
                    mma_f16(o[2 * ntp + 1], pf, vf[2], vf[3]);
                }
            }
        }
        buf = nxt; nxt = nxt + 1 == 3 ? 0 : nxt + 1;
    }

    // final l reduction
    l0r += __shfl_xor_sync(0xffffffffu, l0r, 1);
    l0r += __shfl_xor_sync(0xffffffffu, l0r, 2);
    l1r += __shfl_xor_sync(0xffffffffu, l1r, 1);
    l1r += __shfl_xor_sync(0xffffffffu, l1r, 2);

    const float inv0 = 1.0f / l0r, inv1 = 1.0f / l1r;
    const int gr = lane >> 2, gc = (lane & 3) * 2;
    const size_t row0 = (size_t)(b * SEQ + q0 + wid * 16 + gr) * EMBED + h * HD;
    const size_t row1 = row0 + 8 * EMBED;
#pragma unroll
    for (int nt = 0; nt < 8; nt++) {
        const int d = nt * 8 + gc;
        *(uint32_t*)(oo + row0 + d) = pack_h2(o[nt][0] * inv0, o[nt][1] * inv0);
        *(uint32_t*)(oo + row1 + d) = pack_h2(o[nt][2] * inv1, o[nt][3] * inv1);
    }
}

// ---------------------------------------------------------------------------
extern "C" void kernel_launch(void* const* d_in, const int* in_sizes, int n_in,
                              void* d_out, int out_size)
{
    const float* x     = (const float*)d_in[0];
    const float* W_qkv = (const float*)d_in[1];
    const float* b_qkv = (const float*)d_in[2];
    const float* W_p   = (const float*)d_in[3];
    const float* b_p   = (const float*)d_in[4];
    float* out = (float*)d_out;

    __half *xh, *wq, *wp, *at, *q, *k, *v;
    cudaGetSymbolAddress((void**)&xh, g_x);
    cudaGetSymbolAddress((void**)&wq, g_wqkv);
    cudaGetSymbolAddress((void**)&wp, g_wp);
    cudaGetSymbolAddress((void**)&at, g_at);
    cudaGetSymbolAddress((void**)&q,  g_q);
    cudaGetSymbolAddress((void**)&k,  g_k);
    cudaGetSymbolAddress((void**)&v,  g_v);

    cudaFuncSetAttribute(gemm_f16<0>, cudaFuncAttributeMaxDynamicSharedMemorySize, G_SMEM);
    cudaFuncSetAttribute(gemm_f16<1>, cudaFuncAttributeMaxDynamicSharedMemorySize, G_SMEM);
    cudaFuncSetAttribute(flash_f16,   cudaFuncAttributeMaxDynamicSharedMemorySize, F_SMEM);

    // all conversions in one launch
    {
        int total = NX4 + NQ4 + NP4;
        tohalf_all<<<(total + 255) / 256, 256>>>(
            (const float4*)x, (const float4*)W_qkv, (const float4*)W_p);
    }

    // QKV projection -> per-head q/k/v
    gemm_f16<1><<<dim3(QKV_N / 128, TOKENS / 128), 256, G_SMEM>>>(
        xh, wq, b_qkv, nullptr, TOKENS, QKV_N, EMBED);

    // attention
    flash_f16<<<dim3(SEQ / BQ, NHEAD, BATCH), 256, F_SMEM>>>(q, k, v, at);

    // output projection
    gemm_f16<0><<<dim3(EMBED / 128, TOKENS / 128), 256, G_SMEM>>>(
        at, wp, b_p, out, TOKENS, EMBED, EMBED);
}